// round 8
// baseline (speedup 1.0000x reference)
#include <cuda_runtime.h>
#include <cstdint>

// R7 retry: identical design to the R7 submission; previous run died to a
// container-infra failure before executing.

#define B_TOT 16384
#define F 39
#define E 16
#define D 16
#define NT 128
#define WPS 20   // sWT row stride (floats)
#define PS 16    // sproj row stride: tight, conflict-freedom via offsets mod 32

// transposed-weight offsets in sWT (stride WPS, [j][i] layout)
#define WT_Q 0
#define WT_K 320
#define WT_V 656
#define WT_R 976
#define WT_SZ 1296

// per-batch projection offsets (stride PS=16, 39 rows each = 624 floats)
// mod-32 banks: Q=0, K=16, V=16, R=0 -> half-warp store pairs (Q|V), (K|R) disjoint
#define OFF_Q 0
#define OFF_K 624
#define OFF_V 1264   // 1264 % 32 == 16
#define OFF_R 1888   // 1888 % 32 == 0
#define SPROJ_SZ 2512  // per-batch slab; *4 bytes is 16B-aligned

__device__ __forceinline__ void fma2(uint64_t& d, uint64_t a, uint64_t b) {
    asm("fma.rn.f32x2 %0, %1, %2, %0;" : "+l"(d) : "l"(a), "l"(b));
}
__device__ __forceinline__ uint64_t pk2(float lo, float hi) {
    uint64_t r; asm("mov.b64 %0, {%1, %2};" : "=l"(r) : "f"(lo), "f"(hi)); return r;
}
__device__ __forceinline__ float hadd2(uint64_t p) {
    float lo, hi; asm("mov.b64 {%0, %1}, %2;" : "=f"(lo), "=f"(hi) : "l"(p)); return lo + hi;
}
__device__ __forceinline__ void unpk2(uint64_t p, float& lo, float& hi) {
    asm("mov.b64 {%0, %1}, %2;" : "=f"(lo), "=f"(hi) : "l"(p));
}

__global__ __launch_bounds__(NT, 7)
void self_attn_interaction_kernel(
    const float* __restrict__ x,
    const float* __restrict__ Wq,
    const float* __restrict__ Wk,
    const float* __restrict__ Wv,
    const float* __restrict__ Wr,
    float* __restrict__ out)
{
    __shared__ __align__(16) float sWT[WT_SZ];
    __shared__ __align__(16) float sx[2 * F * E];
    __shared__ __align__(16) float sproj[2 * SPROJ_SZ];

    const int t = threadIdx.x;
    const int b0 = blockIdx.x * 2;
    const float* xb = x + (size_t)b0 * (F * E);

    // ---- stage: weights (transposed into [j][i]) + x for both batches ----
    for (int e = t; e < E * D; e += NT) {
        const int i = e >> 4, j = e & 15;
        const int o = j * WPS + i;
        sWT[WT_Q + o] = Wq[e];
        sWT[WT_K + o] = Wk[e];
        sWT[WT_V + o] = Wv[e];
        sWT[WT_R + o] = Wr[e];
    }
    {
        const float4* x4 = (const float4*)xb;
        float4* sx4 = (float4*)sx;
        for (int i = t; i < (2 * F * E) / 4; i += NT) sx4[i] = x4[i];
    }
    __syncthreads();

    // ---- phase 1: projections for both batches ----
    // thread = (j, s): s bit0 = pair, bit1 = batch, bit2 = f-half.
    // warp covers s = {2w, 2w+1}: x-row loads are full-warp broadcasts,
    // store pair bases are 16 banks apart (offset scheme above).
    {
        const int j  = t & 15;
        const int s  = t >> 4;
        const int p  = s & 1;
        const int bt = (s >> 1) & 1;
        const int f0 = s >> 2;
        const float* sxb = sx + bt * (F * E);
        float* spb = sproj + bt * SPROJ_SZ;
        const ulonglong2* wta = (const ulonglong2*)(sWT + (p ? WT_V : WT_Q) + j * WPS);
        const ulonglong2* wtb = (const ulonglong2*)(sWT + (p ? WT_R : WT_K) + j * WPS);
        float* outA = spb + (p ? OFF_V : OFF_Q);
        float* outB = spb + (p ? OFF_R : OFF_K);

        uint64_t wa[8], wb[8];
        #pragma unroll
        for (int u = 0; u < 4; u++) {
            ulonglong2 a = wta[u], c = wtb[u];
            wa[2 * u] = a.x; wa[2 * u + 1] = a.y;
            wb[2 * u] = c.x; wb[2 * u + 1] = c.y;
        }
        for (int f = f0; f < F; f += 2) {
            const ulonglong2* xr2 = (const ulonglong2*)(sxb + f * 16);
            uint64_t xp[8];
            #pragma unroll
            for (int u = 0; u < 4; u++) {
                ulonglong2 v = xr2[u];
                xp[2 * u] = v.x; xp[2 * u + 1] = v.y;
            }
            uint64_t accA = 0ull, accB = 0ull;
            #pragma unroll
            for (int i = 0; i < 8; i++) {
                fma2(accA, xp[i], wa[i]);
                fma2(accB, xp[i], wb[i]);
            }
            outA[f * PS + j] = hadd2(accA);
            outB[f * PS + j] = hadd2(accB);
        }
    }
    __syncthreads();

    // ---- fused phase 2+3: warp-per-(batch,head) streaming softmax-attention ----
    // warp w: batch = w>>1, head = w&1. lane l owns row l; lanes 0..6 also row l+32.
    {
        const int w  = t >> 5;
        const int bt = w >> 1;
        const int h  = w & 1;
        const int l  = t & 31;
        const int f0 = l;
        const int f1 = l + 32;
        const bool two = (f1 < F);
        const float* spb = sproj + bt * SPROJ_SZ;

        const ulonglong2* q2a = (const ulonglong2*)(spb + OFF_Q + f0 * PS + h * 8);
        ulonglong2 qa = q2a[0], qb = q2a[1];
        uint64_t q00 = qa.x, q01 = qa.y, q02 = qb.x, q03 = qb.y;

        uint64_t q10 = 0, q11 = 0, q12 = 0, q13 = 0;
        if (two) {
            const ulonglong2* q2b = (const ulonglong2*)(spb + OFF_Q + f1 * PS + h * 8);
            ulonglong2 qc = q2b[0], qd = q2b[1];
            q10 = qc.x; q11 = qc.y; q12 = qd.x; q13 = qd.y;
        }

        uint64_t a00 = 0, a01 = 0, a02 = 0, a03 = 0;
        uint64_t a10 = 0, a11 = 0, a12 = 0, a13 = 0;
        float sum0 = 0.f, sum1 = 0.f;

        const float* kbase = spb + OFF_K + h * 8;
        const float* vbase = spb + OFF_V + h * 8;

        #pragma unroll 3
        for (int g = 0; g < F; g++) {
            const ulonglong2* k2 = (const ulonglong2*)(kbase + g * PS);
            const ulonglong2* v2 = (const ulonglong2*)(vbase + g * PS);
            ulonglong2 ku = k2[0], kv = k2[1];
            ulonglong2 vu = v2[0], vv = v2[1];

            // row 0: single packed accumulator for the score dot-product
            {
                uint64_t sp = 0ull;
                fma2(sp, q00, ku.x); fma2(sp, q01, ku.y);
                fma2(sp, q02, kv.x); fma2(sp, q03, kv.y);
                float e = __expf(hadd2(sp));
                sum0 += e;
                uint64_t ee = pk2(e, e);
                fma2(a00, ee, vu.x); fma2(a01, ee, vu.y);
                fma2(a02, ee, vv.x); fma2(a03, ee, vv.y);
            }
            // row 1 (predicated)
            if (two) {
                uint64_t sp = 0ull;
                fma2(sp, q10, ku.x); fma2(sp, q11, ku.y);
                fma2(sp, q12, kv.x); fma2(sp, q13, kv.y);
                float e = __expf(hadd2(sp));
                sum1 += e;
                uint64_t ee = pk2(e, e);
                fma2(a10, ee, vu.x); fma2(a11, ee, vu.y);
                fma2(a12, ee, vv.x); fma2(a13, ee, vv.y);
            }
        }

        float* obase = out + (size_t)(b0 + bt) * (F * E);

        // epilogue row 0
        {
            const float rinv = __fdividef(1.f, sum0);
            const uint64_t rp = pk2(rinv, rinv);
            const ulonglong2* r2 = (const ulonglong2*)(spb + OFF_R + f0 * PS + h * 8);
            ulonglong2 ru = r2[0], rv = r2[1];
            uint64_t o0 = ru.x, o1 = ru.y, o2 = rv.x, o3 = rv.y;
            fma2(o0, a00, rp); fma2(o1, a01, rp);
            fma2(o2, a02, rp); fma2(o3, a03, rp);
            float4 w0, w1;
            unpk2(o0, w0.x, w0.y); unpk2(o1, w0.z, w0.w);
            unpk2(o2, w1.x, w1.y); unpk2(o3, w1.z, w1.w);
            w0.x = fmaxf(w0.x, 0.f); w0.y = fmaxf(w0.y, 0.f);
            w0.z = fmaxf(w0.z, 0.f); w0.w = fmaxf(w0.w, 0.f);
            w1.x = fmaxf(w1.x, 0.f); w1.y = fmaxf(w1.y, 0.f);
            w1.z = fmaxf(w1.z, 0.f); w1.w = fmaxf(w1.w, 0.f);
            float* ob = obase + f0 * 16 + h * 8;
            ((float4*)ob)[0] = w0;
            ((float4*)ob)[1] = w1;
        }
        // epilogue row 1 (predicated)
        if (two) {
            const float rinv = __fdividef(1.f, sum1);
            const uint64_t rp = pk2(rinv, rinv);
            const ulonglong2* r2 = (const ulonglong2*)(spb + OFF_R + f1 * PS + h * 8);
            ulonglong2 ru = r2[0], rv = r2[1];
            uint64_t o0 = ru.x, o1 = ru.y, o2 = rv.x, o3 = rv.y;
            fma2(o0, a10, rp); fma2(o1, a11, rp);
            fma2(o2, a12, rp); fma2(o3, a13, rp);
            float4 w0, w1;
            unpk2(o0, w0.x, w0.y); unpk2(o1, w0.z, w0.w);
            unpk2(o2, w1.x, w1.y); unpk2(o3, w1.z, w1.w);
            w0.x = fmaxf(w0.x, 0.f); w0.y = fmaxf(w0.y, 0.f);
            w0.z = fmaxf(w0.z, 0.f); w0.w = fmaxf(w0.w, 0.f);
            w1.x = fmaxf(w1.x, 0.f); w1.y = fmaxf(w1.y, 0.f);
            w1.z = fmaxf(w1.z, 0.f); w1.w = fmaxf(w1.w, 0.f);
            float* ob = obase + f1 * 16 + h * 8;
            ((float4*)ob)[0] = w0;
            ((float4*)ob)[1] = w1;
        }
    }
}

extern "C" void kernel_launch(void* const* d_in, const int* in_sizes, int n_in,
                              void* d_out, int out_size)
{
    const float* x  = (const float*)d_in[0];
    const float* Wq = (const float*)d_in[1];
    const float* Wk = (const float*)d_in[2];
    const float* Wv = (const float*)d_in[3];
    const float* Wr = (const float*)d_in[4];
    float* out = (float*)d_out;
    self_attn_interaction_kernel<<<B_TOT / 2, NT>>>(x, Wq, Wk, Wv, Wr, out);
}

// round 10
// speedup vs baseline: 1.8081x; 1.8081x over previous
#include <cuda_runtime.h>
#include <cstdint>

// R9 retry: identical to the R8 submission (tf32 mma rewrite); both prior runs
// died to container-infra failures before executing. Re-audited for layout and
// bounds correctness this round; no changes needed.

#define B_TOT 16384
#define F 39
#define NT 128

// shared-memory layout (float units), total 9728 floats = 38 KB
#define SW_OFF   0          // 4 weight mats, 16x16 row-major, contiguous (256 each)
#define QKVR_OFF 1024       // 2 batches x {Q,K,V,R}, each 40 rows x stride 20
#define XP_OFF   7424       // union: sx (2 x 48 x 20) | pbuf (4 warps x 48 x 12)
#define SMEM_F   9728
#define QS 20               // Q/K/V/R and sx row stride: grp*20+tig is a bank permutation
#define PBS 12              // pbuf row stride: grp*12+tig is a bank permutation

__device__ __forceinline__ uint32_t f2tf(float f) {
    uint32_t r; asm("cvt.rna.tf32.f32 %0, %1;" : "=r"(r) : "f"(f)); return r;
}
__device__ __forceinline__ void mma8(float& c0, float& c1, float& c2, float& c3,
                                     uint32_t a0, uint32_t a1, uint32_t a2, uint32_t a3,
                                     uint32_t b0, uint32_t b1) {
    asm("mma.sync.aligned.m16n8k8.row.col.f32.tf32.tf32.f32 "
        "{%0,%1,%2,%3}, {%4,%5,%6,%7}, {%8,%9}, {%0,%1,%2,%3};"
        : "+f"(c0), "+f"(c1), "+f"(c2), "+f"(c3)
        : "r"(a0), "r"(a1), "r"(a2), "r"(a3), "r"(b0), "r"(b1));
}

__global__ __launch_bounds__(NT)
void self_attn_mma_kernel(
    const float* __restrict__ x,
    const float* __restrict__ Wq,
    const float* __restrict__ Wk,
    const float* __restrict__ Wv,
    const float* __restrict__ Wr,
    float* __restrict__ out)
{
    __shared__ __align__(16) float smem[SMEM_F];

    const int t    = threadIdx.x;
    const int lane = t & 31;
    const int grp  = lane >> 2;          // 0..7
    const int tig  = lane & 3;           // 0..3
    const int w    = t >> 5;             // warp 0..3
    const int bt   = w >> 1;             // batch within pair
    const int p    = w & 1;              // 0: {Q,K} proj + head 0 ; 1: {V,R} proj + head 1
    const int b0   = blockIdx.x * 2;

    // ---------------- stage: weights + x (rows 39..47 zeroed) ----------------
    for (int i = t; i < 256; i += NT) {  // 4 mats x 64 float4
        const int m = i >> 6, r = i & 63;
        const float4* src = (const float4*)(m == 0 ? Wq : m == 1 ? Wk : m == 2 ? Wv : Wr);
        ((float4*)(smem + SW_OFF))[m * 64 + r] = src[r];
    }
    {
        const float* xb = x + (size_t)b0 * (F * 16);
        for (int i = t; i < 2 * F * 4; i += NT) {
            const int bb = i / (F * 4), r = i - bb * (F * 4);
            const int f = r >> 2, c = r & 3;
            float4 v = ((const float4*)(xb + bb * F * 16 + f * 16))[c];
            *(float4*)(smem + XP_OFF + bb * 960 + f * QS + c * 4) = v;
        }
        for (int i = t; i < 2 * 9 * 4; i += NT) {
            const int bb = i / 36, r = i - bb * 36;
            const int f = F + (r >> 2), c = r & 3;
            *(float4*)(smem + XP_OFF + bb * 960 + f * QS + c * 4) = make_float4(0.f, 0.f, 0.f, 0.f);
        }
    }
    __syncthreads();

    // ---------------- phase 1: projections via mma (warp -> batch bt, W-pair p) ----
    {
        float* spb  = smem + QKVR_OFF + bt * 3200;
        float* outA = spb + (p ? 1600 : 0);     // V : Q
        float* outB = spb + (p ? 2400 : 800);   // R : K
        const float* WA = smem + SW_OFF + (p ? 2 : 0) * 256;
        const float* WB = smem + SW_OFF + (p ? 3 : 1) * 256;
        const float* sxb = smem + XP_OFF + bt * 960;

        uint32_t bA[2][2][2], bB[2][2][2];      // [kt][nt][2]
        #pragma unroll
        for (int kt = 0; kt < 2; kt++)
            #pragma unroll
            for (int nt = 0; nt < 2; nt++) {
                bA[kt][nt][0] = f2tf(WA[(kt * 8 + tig) * 16 + nt * 8 + grp]);
                bA[kt][nt][1] = f2tf(WA[(kt * 8 + tig + 4) * 16 + nt * 8 + grp]);
                bB[kt][nt][0] = f2tf(WB[(kt * 8 + tig) * 16 + nt * 8 + grp]);
                bB[kt][nt][1] = f2tf(WB[(kt * 8 + tig + 4) * 16 + nt * 8 + grp]);
            }

        #pragma unroll
        for (int mt = 0; mt < 3; mt++) {
            const int m0 = mt * 16;
            uint32_t a[2][4];
            #pragma unroll
            for (int kt = 0; kt < 2; kt++) {
                a[kt][0] = f2tf(sxb[(m0 + grp) * QS + kt * 8 + tig]);
                a[kt][1] = f2tf(sxb[(m0 + grp + 8) * QS + kt * 8 + tig]);
                a[kt][2] = f2tf(sxb[(m0 + grp) * QS + kt * 8 + tig + 4]);
                a[kt][3] = f2tf(sxb[(m0 + grp + 8) * QS + kt * 8 + tig + 4]);
            }
            #pragma unroll
            for (int nt = 0; nt < 2; nt++) {
                float cA0 = 0.f, cA1 = 0.f, cA2 = 0.f, cA3 = 0.f;
                float cB0 = 0.f, cB1 = 0.f, cB2 = 0.f, cB3 = 0.f;
                mma8(cA0, cA1, cA2, cA3, a[0][0], a[0][1], a[0][2], a[0][3], bA[0][nt][0], bA[0][nt][1]);
                mma8(cA0, cA1, cA2, cA3, a[1][0], a[1][1], a[1][2], a[1][3], bA[1][nt][0], bA[1][nt][1]);
                mma8(cB0, cB1, cB2, cB3, a[0][0], a[0][1], a[0][2], a[0][3], bB[0][nt][0], bB[0][nt][1]);
                mma8(cB0, cB1, cB2, cB3, a[1][0], a[1][1], a[1][2], a[1][3], bB[1][nt][0], bB[1][nt][1]);
                const int c = nt * 8 + 2 * tig;
                *(float2*)&outA[(m0 + grp) * QS + c] = make_float2(cA0, cA1);
                *(float2*)&outB[(m0 + grp) * QS + c] = make_float2(cB0, cB1);
                if (mt < 2) {   // rows m0+grp+8 <= 31; mt2 high rows (40..47) not allocated
                    *(float2*)&outA[(m0 + grp + 8) * QS + c] = make_float2(cA2, cA3);
                    *(float2*)&outB[(m0 + grp + 8) * QS + c] = make_float2(cB2, cB3);
                }
            }
        }
    }
    __syncthreads();

    // ---------------- phase 2+3: attention via mma (warp -> batch bt, head p) ------
    {
        const int h = p;
        const float* spb = smem + QKVR_OFF + bt * 3200;
        const float* Q = spb, * K = spb + 800, * V = spb + 1600, * R = spb + 2400;
        uint32_t* pb = (uint32_t*)smem + XP_OFF + w * 576;

        // Q A-frags (k = d = 8, one k-step). Rows 40..47 of "Q" alias K rows 0..7:
        // harmless — those score rows are never emitted.
        uint32_t qa[3][4];
        #pragma unroll
        for (int mt = 0; mt < 3; mt++) {
            const int m0 = mt * 16;
            qa[mt][0] = f2tf(Q[(m0 + grp) * QS + h * 8 + tig]);
            qa[mt][1] = f2tf(Q[(m0 + grp + 8) * QS + h * 8 + tig]);
            qa[mt][2] = f2tf(Q[(m0 + grp) * QS + h * 8 + tig + 4]);
            qa[mt][3] = f2tf(Q[(m0 + grp + 8) * QS + h * 8 + tig + 4]);
        }
        // K B-frags: b0 = K[g0+grp][h*8+tig], b1 = +4 col
        uint32_t kb[5][2];
        #pragma unroll
        for (int nt = 0; nt < 5; nt++) {
            kb[nt][0] = f2tf(K[(nt * 8 + grp) * QS + h * 8 + tig]);
            kb[nt][1] = f2tf(K[(nt * 8 + grp) * QS + h * 8 + tig + 4]);
        }

        float o[3][4] = {{0.f}};
        float rsl[3] = {0.f, 0.f, 0.f}, rsh[3] = {0.f, 0.f, 0.f};

        #pragma unroll
        for (int nt = 0; nt < 5; nt++) {
            // S tiles -> exp -> stage P tile (48 x 8, tf32-encoded)
            #pragma unroll
            for (int mt = 0; mt < 3; mt++) {
                const int m0 = mt * 16;
                float c0 = 0.f, c1 = 0.f, c2 = 0.f, c3 = 0.f;
                mma8(c0, c1, c2, c3, qa[mt][0], qa[mt][1], qa[mt][2], qa[mt][3],
                     kb[nt][0], kb[nt][1]);
                float e0 = __expf(c0), e1 = __expf(c1), e2 = __expf(c2), e3 = __expf(c3);
                rsl[mt] += e0 + e1;
                rsh[mt] += e2 + e3;
                uint2 lo = make_uint2(f2tf(e0), f2tf(e1));
                uint2 hi = make_uint2(f2tf(e2), f2tf(e3));
                *(uint2*)&pb[(m0 + grp) * PBS + 2 * tig] = lo;
                *(uint2*)&pb[(m0 + grp + 8) * PBS + 2 * tig] = hi;
            }
            __syncwarp();
            // V B-frag for this k-tile: b0 = V[g0+tig][h*8+grp], b1 = +4 row
            uint32_t vb0 = f2tf(V[(nt * 8 + tig) * QS + h * 8 + grp]);
            uint32_t vb1 = f2tf(V[(nt * 8 + tig + 4) * QS + h * 8 + grp]);
            #pragma unroll
            for (int mt = 0; mt < 3; mt++) {
                const int m0 = mt * 16;
                uint32_t pa0 = pb[(m0 + grp) * PBS + tig];
                uint32_t pa1 = pb[(m0 + grp + 8) * PBS + tig];
                uint32_t pa2 = pb[(m0 + grp) * PBS + tig + 4];
                uint32_t pa3 = pb[(m0 + grp + 8) * PBS + tig + 4];
                mma8(o[mt][0], o[mt][1], o[mt][2], o[mt][3], pa0, pa1, pa2, pa3, vb0, vb1);
            }
            __syncwarp();   // protect pbuf reuse next iteration
        }

        // row sums: quad-reduce, subtract the exact pad-column contribution (e = 1)
        float rl[3], rh[3];
        #pragma unroll
        for (int mt = 0; mt < 3; mt++) {
            float a = rsl[mt], b = rsh[mt];
            a += __shfl_xor_sync(0xffffffffu, a, 1);
            a += __shfl_xor_sync(0xffffffffu, a, 2);
            b += __shfl_xor_sync(0xffffffffu, b, 1);
            b += __shfl_xor_sync(0xffffffffu, b, 2);
            rl[mt] = __fdividef(1.f, a - 1.f);
            rh[mt] = __fdividef(1.f, b - 1.f);
        }

        // epilogue: normalize, + residual, ReLU, store
        float* ob = out + (size_t)(b0 + bt) * (F * 16);
        #pragma unroll
        for (int mt = 0; mt < 3; mt++) {
            const int m0 = mt * 16;
            const int r0 = m0 + grp, r1 = m0 + grp + 8;
            const int c = h * 8 + 2 * tig;
            if (r0 < F) {
                float2 rr = *(float2*)&R[r0 * QS + c];
                float v0 = fmaxf(o[mt][0] * rl[mt] + rr.x, 0.f);
                float v1 = fmaxf(o[mt][1] * rl[mt] + rr.y, 0.f);
                *(float2*)&ob[r0 * 16 + c] = make_float2(v0, v1);
            }
            if (r1 < F) {
                float2 rr = *(float2*)&R[r1 * QS + c];
                float v0 = fmaxf(o[mt][2] * rh[mt] + rr.x, 0.f);
                float v1 = fmaxf(o[mt][3] * rh[mt] + rr.y, 0.f);
                *(float2*)&ob[r1 * 16 + c] = make_float2(v0, v1);
            }
        }
    }
}

extern "C" void kernel_launch(void* const* d_in, const int* in_sizes, int n_in,
                              void* d_out, int out_size)
{
    const float* x  = (const float*)d_in[0];
    const float* Wq = (const float*)d_in[1];
    const float* Wk = (const float*)d_in[2];
    const float* Wv = (const float*)d_in[3];
    const float* Wr = (const float*)d_in[4];
    float* out = (float*)d_out;
    self_attn_mma_kernel<<<B_TOT / 2, NT>>>(x, Wq, Wk, Wv, Wr, out);
}

// round 11
// speedup vs baseline: 1.9365x; 1.0710x over previous
#include <cuda_runtime.h>
#include <cstdint>

#define B_TOT 16384
#define F 39
#define NT 128

// shared-memory layout (float units), total 9344 floats = 36.5 KB -> 6 CTAs/SM
#define SW_OFF   0          // 4 weight mats (tf32 bits), 16x16 row-major, 256 each
#define QKVR_OFF 1024       // 2 batches x {Q,K,V (tf32 bits), R (fp32)}, 40 rows x stride 20
#define SX_OFF   7424       // x staged as tf32 bits: 2 x 48 x 20
#define SMEM_F   9344
#define QS 20               // row stride: grp*20+tig is a bank permutation

__device__ __forceinline__ uint32_t f2tf(float f) {
    uint32_t r; asm("cvt.rna.tf32.f32 %0, %1;" : "=r"(r) : "f"(f)); return r;
}
__device__ __forceinline__ void mma8(float& c0, float& c1, float& c2, float& c3,
                                     uint32_t a0, uint32_t a1, uint32_t a2, uint32_t a3,
                                     uint32_t b0, uint32_t b1) {
    asm("mma.sync.aligned.m16n8k8.row.col.f32.tf32.tf32.f32 "
        "{%0,%1,%2,%3}, {%4,%5,%6,%7}, {%8,%9}, {%0,%1,%2,%3};"
        : "+f"(c0), "+f"(c1), "+f"(c2), "+f"(c3)
        : "r"(a0), "r"(a1), "r"(a2), "r"(a3), "r"(b0), "r"(b1));
}

__global__ __launch_bounds__(NT, 6)
void self_attn_mma_kernel(
    const float* __restrict__ x,
    const float* __restrict__ Wq,
    const float* __restrict__ Wk,
    const float* __restrict__ Wv,
    const float* __restrict__ Wr,
    float* __restrict__ out)
{
    __shared__ __align__(16) float smem[SMEM_F];

    const int t    = threadIdx.x;
    const int lane = t & 31;
    const int grp  = lane >> 2;          // 0..7
    const int tig  = lane & 3;           // 0..3
    const int w    = t >> 5;             // warp 0..3
    const int bt   = w >> 1;             // batch within pair
    const int p    = w & 1;              // 0: {Q,K} proj + head 0 ; 1: {V,R} proj + head 1
    const int b0   = blockIdx.x * 2;

    // ---------------- stage: weights + x, both pre-converted to tf32 bits ----------
    for (int i = t; i < 256; i += NT) {  // 4 mats x 64 float4
        const int m = i >> 6, r = i & 63;
        const float4* src = (const float4*)(m == 0 ? Wq : m == 1 ? Wk : m == 2 ? Wv : Wr);
        float4 v = src[r];
        ((uint4*)(smem + SW_OFF))[m * 64 + r] =
            make_uint4(f2tf(v.x), f2tf(v.y), f2tf(v.z), f2tf(v.w));
    }
    {
        const float* xb = x + (size_t)b0 * (F * 16);
        for (int i = t; i < 2 * F * 4; i += NT) {
            const int bb = i / (F * 4), r = i - bb * (F * 4);
            const int f = r >> 2, c = r & 3;
            float4 v = ((const float4*)(xb + bb * F * 16 + f * 16))[c];
            *(uint4*)(smem + SX_OFF + bb * 960 + f * QS + c * 4) =
                make_uint4(f2tf(v.x), f2tf(v.y), f2tf(v.z), f2tf(v.w));
        }
        for (int i = t; i < 2 * 9 * 4; i += NT) {   // zero pad rows 39..47
            const int bb = i / 36, r = i - bb * 36;
            const int f = F + (r >> 2), c = r & 3;
            *(uint4*)(smem + SX_OFF + bb * 960 + f * QS + c * 4) = make_uint4(0, 0, 0, 0);
        }
    }
    __syncthreads();

    // ---------------- phase 1: projections via mma (warp -> batch bt, W-pair p) ----
    {
        float* spb  = smem + QKVR_OFF + bt * 3200;
        float* outA = spb + (p ? 1600 : 0);     // V : Q   (stored as tf32 bits)
        float* outB = spb + (p ? 2400 : 800);   // R : K   (R fp32, K tf32 bits)
        const uint32_t* WA = (const uint32_t*)(smem + SW_OFF) + (p ? 2 : 0) * 256;
        const uint32_t* WB = (const uint32_t*)(smem + SW_OFF) + (p ? 3 : 1) * 256;
        const uint32_t* sxb = (const uint32_t*)(smem + SX_OFF) + bt * 960;

        uint32_t bA[2][2][2], bB[2][2][2];      // [kt][nt][2], raw tf32 bits
        #pragma unroll
        for (int kt = 0; kt < 2; kt++)
            #pragma unroll
            for (int nt = 0; nt < 2; nt++) {
                bA[kt][nt][0] = WA[(kt * 8 + tig) * 16 + nt * 8 + grp];
                bA[kt][nt][1] = WA[(kt * 8 + tig + 4) * 16 + nt * 8 + grp];
                bB[kt][nt][0] = WB[(kt * 8 + tig) * 16 + nt * 8 + grp];
                bB[kt][nt][1] = WB[(kt * 8 + tig + 4) * 16 + nt * 8 + grp];
            }

        #pragma unroll
        for (int mt = 0; mt < 3; mt++) {
            const int m0 = mt * 16;
            uint32_t a[2][4];
            #pragma unroll
            for (int kt = 0; kt < 2; kt++) {
                a[kt][0] = sxb[(m0 + grp) * QS + kt * 8 + tig];
                a[kt][1] = sxb[(m0 + grp + 8) * QS + kt * 8 + tig];
                a[kt][2] = sxb[(m0 + grp) * QS + kt * 8 + tig + 4];
                a[kt][3] = sxb[(m0 + grp + 8) * QS + kt * 8 + tig + 4];
            }
            #pragma unroll
            for (int nt = 0; nt < 2; nt++) {
                float cA0 = 0.f, cA1 = 0.f, cA2 = 0.f, cA3 = 0.f;
                float cB0 = 0.f, cB1 = 0.f, cB2 = 0.f, cB3 = 0.f;
                mma8(cA0, cA1, cA2, cA3, a[0][0], a[0][1], a[0][2], a[0][3], bA[0][nt][0], bA[0][nt][1]);
                mma8(cA0, cA1, cA2, cA3, a[1][0], a[1][1], a[1][2], a[1][3], bA[1][nt][0], bA[1][nt][1]);
                mma8(cB0, cB1, cB2, cB3, a[0][0], a[0][1], a[0][2], a[0][3], bB[0][nt][0], bB[0][nt][1]);
                mma8(cB0, cB1, cB2, cB3, a[1][0], a[1][1], a[1][2], a[1][3], bB[1][nt][0], bB[1][nt][1]);
                const int c = nt * 8 + 2 * tig;
                // outA (Q or V): always store tf32 bits
                *(float2*)&outA[(m0 + grp) * QS + c] =
                    make_float2(__uint_as_float(f2tf(cA0)), __uint_as_float(f2tf(cA1)));
                // outB: K -> tf32 bits ; R -> fp32 (epilogue precision)
                if (p == 0)
                    *(float2*)&outB[(m0 + grp) * QS + c] =
                        make_float2(__uint_as_float(f2tf(cB0)), __uint_as_float(f2tf(cB1)));
                else
                    *(float2*)&outB[(m0 + grp) * QS + c] = make_float2(cB0, cB1);
                if (mt < 2) {   // high rows only for rows <= 31 (rows 40..47 not allocated)
                    *(float2*)&outA[(m0 + grp + 8) * QS + c] =
                        make_float2(__uint_as_float(f2tf(cA2)), __uint_as_float(f2tf(cA3)));
                    if (p == 0)
                        *(float2*)&outB[(m0 + grp + 8) * QS + c] =
                            make_float2(__uint_as_float(f2tf(cB2)), __uint_as_float(f2tf(cB3)));
                    else
                        *(float2*)&outB[(m0 + grp + 8) * QS + c] = make_float2(cB2, cB3);
                }
            }
        }
    }
    __syncthreads();

    // ---------------- phase 2+3: attention via mma (warp -> batch bt, head p) ------
    {
        const int h = p;
        const float* spb = smem + QKVR_OFF + bt * 3200;
        const uint32_t* Q = (const uint32_t*)spb;        // tf32 bits
        const uint32_t* K = Q + 800;                     // tf32 bits
        const uint32_t* V = Q + 1600;                    // tf32 bits
        const float*    R = spb + 2400;                  // fp32

        // Q A-frags. Rows 40..47 alias K rows 0..7 — garbage rows, never emitted.
        uint32_t qa[3][4];
        #pragma unroll
        for (int mt = 0; mt < 3; mt++) {
            const int m0 = mt * 16;
            qa[mt][0] = Q[(m0 + grp) * QS + h * 8 + tig];
            qa[mt][1] = Q[(m0 + grp + 8) * QS + h * 8 + tig];
            qa[mt][2] = Q[(m0 + grp) * QS + h * 8 + tig + 4];
            qa[mt][3] = Q[(m0 + grp + 8) * QS + h * 8 + tig + 4];
        }
        uint32_t kb[5][2];
        #pragma unroll
        for (int nt = 0; nt < 5; nt++) {
            kb[nt][0] = K[(nt * 8 + grp) * QS + h * 8 + tig];
            kb[nt][1] = K[(nt * 8 + grp) * QS + h * 8 + tig + 4];
        }

        float o[3][4] = {{0.f}};
        float rsl[3] = {0.f, 0.f, 0.f}, rsh[3] = {0.f, 0.f, 0.f};

        const int  srcA = grp * 4 + (tig >> 1);   // shuffle-transpose source lanes
        const int  srcB = srcA + 2;
        const bool hi   = (tig & 1);

        #pragma unroll
        for (int nt = 0; nt < 5; nt++) {
            const uint32_t vb0 = V[(nt * 8 + tig) * QS + h * 8 + grp];
            const uint32_t vb1 = V[(nt * 8 + tig + 4) * QS + h * 8 + grp];
            #pragma unroll
            for (int mt = 0; mt < 3; mt++) {
                float c0 = 0.f, c1 = 0.f, c2 = 0.f, c3 = 0.f;
                mma8(c0, c1, c2, c3, qa[mt][0], qa[mt][1], qa[mt][2], qa[mt][3],
                     kb[nt][0], kb[nt][1]);
                const float e0 = __expf(c0), e1 = __expf(c1);
                const float e2 = __expf(c2), e3 = __expf(c3);
                rsl[mt] += e0 + e1;
                rsh[mt] += e2 + e3;
                const uint32_t u0 = f2tf(e0), u1 = f2tf(e1);
                const uint32_t u2 = f2tf(e2), u3 = f2tf(e3);
                // C-layout (rows grp/grp+8, cols 2tig,2tig+1) -> A-layout (cols tig,tig+4)
                const uint32_t x0  = __shfl_sync(0xffffffffu, u0, srcA);
                const uint32_t x1  = __shfl_sync(0xffffffffu, u1, srcA);
                const uint32_t pa0 = hi ? x1 : x0;
                const uint32_t y0  = __shfl_sync(0xffffffffu, u2, srcA);
                const uint32_t y1  = __shfl_sync(0xffffffffu, u3, srcA);
                const uint32_t pa1 = hi ? y1 : y0;
                const uint32_t x0b = __shfl_sync(0xffffffffu, u0, srcB);
                const uint32_t x1b = __shfl_sync(0xffffffffu, u1, srcB);
                const uint32_t pa2 = hi ? x1b : x0b;
                const uint32_t y0b = __shfl_sync(0xffffffffu, u2, srcB);
                const uint32_t y1b = __shfl_sync(0xffffffffu, u3, srcB);
                const uint32_t pa3 = hi ? y1b : y0b;
                mma8(o[mt][0], o[mt][1], o[mt][2], o[mt][3], pa0, pa1, pa2, pa3, vb0, vb1);
            }
        }

        // row sums: quad-reduce, subtract exact pad-column contribution (e = 1)
        float rl[3], rh[3];
        #pragma unroll
        for (int mt = 0; mt < 3; mt++) {
            float a = rsl[mt], b = rsh[mt];
            a += __shfl_xor_sync(0xffffffffu, a, 1);
            a += __shfl_xor_sync(0xffffffffu, a, 2);
            b += __shfl_xor_sync(0xffffffffu, b, 1);
            b += __shfl_xor_sync(0xffffffffu, b, 2);
            rl[mt] = __fdividef(1.f, a - 1.f);
            rh[mt] = __fdividef(1.f, b - 1.f);
        }

        // epilogue: normalize, + residual, ReLU, store
        float* ob = out + (size_t)(b0 + bt) * (F * 16);
        #pragma unroll
        for (int mt = 0; mt < 3; mt++) {
            const int m0 = mt * 16;
            const int r0 = m0 + grp, r1 = m0 + grp + 8;
            const int c = h * 8 + 2 * tig;
            if (r0 < F) {
                float2 rr = *(float2*)&R[r0 * QS + c];
                float v0 = fmaxf(o[mt][0] * rl[mt] + rr.x, 0.f);
                float v1 = fmaxf(o[mt][1] * rl[mt] + rr.y, 0.f);
                *(float2*)&ob[r0 * 16 + c] = make_float2(v0, v1);
            }
            if (r1 < F) {
                float2 rr = *(float2*)&R[r1 * QS + c];
                float v0 = fmaxf(o[mt][2] * rh[mt] + rr.x, 0.f);
                float v1 = fmaxf(o[mt][3] * rh[mt] + rr.y, 0.f);
                *(float2*)&ob[r1 * 16 + c] = make_float2(v0, v1);
            }
        }
    }
}

extern "C" void kernel_launch(void* const* d_in, const int* in_sizes, int n_in,
                              void* d_out, int out_size)
{
    const float* x  = (const float*)d_in[0];
    const float* Wq = (const float*)d_in[1];
    const float* Wk = (const float*)d_in[2];
    const float* Wv = (const float*)d_in[3];
    const float* Wr = (const float*)d_in[4];
    float* out = (float*)d_out;
    self_attn_mma_kernel<<<B_TOT / 2, NT>>>(x, Wq, Wk, Wv, Wr, out);
}

// round 12
// speedup vs baseline: 2.4010x; 1.2399x over previous
#include <cuda_runtime.h>
#include <cstdint>

#define B_TOT 16384
#define F 39
#define NT 128

// shared-memory layout (float units), total 9344 floats = 36.5 KB -> 6 CTAs/SM
#define SW_OFF   0          // 4 weight mats (tf32 bits), 16x16 row-major, 256 each
#define QKVR_OFF 1024       // 2 batches x {Q,K (tf32 bits), V,R (fp32)}, 40 rows x stride 20
#define SX_OFF   7424       // x staged as tf32 bits: 2 x 48 x 20
#define SMEM_F   9344
#define QS 20               // row stride: grp*20+tig is a bank permutation

__device__ __forceinline__ uint32_t f2tf(float f) {
    uint32_t r; asm("cvt.rna.tf32.f32 %0, %1;" : "=r"(r) : "f"(f)); return r;
}
// pack {lo, hi} floats -> bf16x2 (lo in lower half)
__device__ __forceinline__ uint32_t pkbf(float lo, float hi) {
    uint32_t r; asm("cvt.rn.bf16x2.f32 %0, %1, %2;" : "=r"(r) : "f"(hi), "f"(lo)); return r;
}
__device__ __forceinline__ void mma8(float& c0, float& c1, float& c2, float& c3,
                                     uint32_t a0, uint32_t a1, uint32_t a2, uint32_t a3,
                                     uint32_t b0, uint32_t b1) {
    asm("mma.sync.aligned.m16n8k8.row.col.f32.tf32.tf32.f32 "
        "{%0,%1,%2,%3}, {%4,%5,%6,%7}, {%8,%9}, {%0,%1,%2,%3};"
        : "+f"(c0), "+f"(c1), "+f"(c2), "+f"(c3)
        : "r"(a0), "r"(a1), "r"(a2), "r"(a3), "r"(b0), "r"(b1));
}
__device__ __forceinline__ void mma8bf(float& c0, float& c1, float& c2, float& c3,
                                       uint32_t a0, uint32_t a1, uint32_t b0) {
    asm("mma.sync.aligned.m16n8k8.row.col.f32.bf16.bf16.f32 "
        "{%0,%1,%2,%3}, {%4,%5}, {%6}, {%0,%1,%2,%3};"
        : "+f"(c0), "+f"(c1), "+f"(c2), "+f"(c3)
        : "r"(a0), "r"(a1), "r"(b0));
}

__global__ __launch_bounds__(NT, 6)
void self_attn_mma_kernel(
    const float* __restrict__ x,
    const float* __restrict__ Wq,
    const float* __restrict__ Wk,
    const float* __restrict__ Wv,
    const float* __restrict__ Wr,
    float* __restrict__ out)
{
    __shared__ __align__(16) float smem[SMEM_F];

    const int t    = threadIdx.x;
    const int lane = t & 31;
    const int grp  = lane >> 2;          // 0..7
    const int tig  = lane & 3;           // 0..3
    const int w    = t >> 5;             // warp 0..3
    const int bt   = w >> 1;             // batch within pair
    const int p    = w & 1;              // 0: {Q,K} proj + head 0 ; 1: {V,R} proj + head 1
    const int b0   = blockIdx.x * 2;

    // ---------------- stage: weights + x, pre-converted to tf32 bits ----------
    for (int i = t; i < 256; i += NT) {  // 4 mats x 64 float4
        const int m = i >> 6, r = i & 63;
        const float4* src = (const float4*)(m == 0 ? Wq : m == 1 ? Wk : m == 2 ? Wv : Wr);
        float4 v = src[r];
        ((uint4*)(smem + SW_OFF))[m * 64 + r] =
            make_uint4(f2tf(v.x), f2tf(v.y), f2tf(v.z), f2tf(v.w));
    }
    {
        const float* xb = x + (size_t)b0 * (F * 16);
        for (int i = t; i < 2 * F * 4; i += NT) {
            const int bb = i / (F * 4), r = i - bb * (F * 4);
            const int f = r >> 2, c = r & 3;
            float4 v = ((const float4*)(xb + bb * F * 16 + f * 16))[c];
            *(uint4*)(smem + SX_OFF + bb * 960 + f * QS + c * 4) =
                make_uint4(f2tf(v.x), f2tf(v.y), f2tf(v.z), f2tf(v.w));
        }
        for (int i = t; i < 2 * 9 * 4; i += NT) {   // zero pad rows 39..47
            const int bb = i / 36, r = i - bb * 36;
            const int f = F + (r >> 2), c = r & 3;
            *(uint4*)(smem + SX_OFF + bb * 960 + f * QS + c * 4) = make_uint4(0, 0, 0, 0);
        }
    }
    __syncthreads();

    // ---------------- phase 1: projections via mma (warp -> batch bt, W-pair p) ----
    // p==0 outputs {Q,K} stored as tf32 bits; p==1 outputs {V,R} stored fp32.
    {
        float* spb  = smem + QKVR_OFF + bt * 3200;
        float* outA = spb + (p ? 1600 : 0);     // V : Q
        float* outB = spb + (p ? 2400 : 800);   // R : K
        const uint32_t* WA = (const uint32_t*)(smem + SW_OFF) + (p ? 2 : 0) * 256;
        const uint32_t* WB = (const uint32_t*)(smem + SW_OFF) + (p ? 3 : 1) * 256;
        const uint32_t* sxb = (const uint32_t*)(smem + SX_OFF) + bt * 960;

        uint32_t bA[2][2][2], bB[2][2][2];      // [kt][nt][2], raw tf32 bits
        #pragma unroll
        for (int kt = 0; kt < 2; kt++)
            #pragma unroll
            for (int nt = 0; nt < 2; nt++) {
                bA[kt][nt][0] = WA[(kt * 8 + tig) * 16 + nt * 8 + grp];
                bA[kt][nt][1] = WA[(kt * 8 + tig + 4) * 16 + nt * 8 + grp];
                bB[kt][nt][0] = WB[(kt * 8 + tig) * 16 + nt * 8 + grp];
                bB[kt][nt][1] = WB[(kt * 8 + tig + 4) * 16 + nt * 8 + grp];
            }

        #pragma unroll
        for (int mt = 0; mt < 3; mt++) {
            const int m0 = mt * 16;
            uint32_t a[2][4];
            #pragma unroll
            for (int kt = 0; kt < 2; kt++) {
                a[kt][0] = sxb[(m0 + grp) * QS + kt * 8 + tig];
                a[kt][1] = sxb[(m0 + grp + 8) * QS + kt * 8 + tig];
                a[kt][2] = sxb[(m0 + grp) * QS + kt * 8 + tig + 4];
                a[kt][3] = sxb[(m0 + grp + 8) * QS + kt * 8 + tig + 4];
            }
            #pragma unroll
            for (int nt = 0; nt < 2; nt++) {
                float cA0 = 0.f, cA1 = 0.f, cA2 = 0.f, cA3 = 0.f;
                float cB0 = 0.f, cB1 = 0.f, cB2 = 0.f, cB3 = 0.f;
                mma8(cA0, cA1, cA2, cA3, a[0][0], a[0][1], a[0][2], a[0][3], bA[0][nt][0], bA[0][nt][1]);
                mma8(cA0, cA1, cA2, cA3, a[1][0], a[1][1], a[1][2], a[1][3], bA[1][nt][0], bA[1][nt][1]);
                mma8(cB0, cB1, cB2, cB3, a[0][0], a[0][1], a[0][2], a[0][3], bB[0][nt][0], bB[0][nt][1]);
                mma8(cB0, cB1, cB2, cB3, a[1][0], a[1][1], a[1][2], a[1][3], bB[1][nt][0], bB[1][nt][1]);
                const int c = nt * 8 + 2 * tig;
                if (p == 0) {   // Q, K as tf32 bits
                    *(float2*)&outA[(m0 + grp) * QS + c] =
                        make_float2(__uint_as_float(f2tf(cA0)), __uint_as_float(f2tf(cA1)));
                    *(float2*)&outB[(m0 + grp) * QS + c] =
                        make_float2(__uint_as_float(f2tf(cB0)), __uint_as_float(f2tf(cB1)));
                } else {        // V, R as fp32
                    *(float2*)&outA[(m0 + grp) * QS + c] = make_float2(cA0, cA1);
                    *(float2*)&outB[(m0 + grp) * QS + c] = make_float2(cB0, cB1);
                }
                if (mt < 2) {   // high rows only for rows <= 31
                    if (p == 0) {
                        *(float2*)&outA[(m0 + grp + 8) * QS + c] =
                            make_float2(__uint_as_float(f2tf(cA2)), __uint_as_float(f2tf(cA3)));
                        *(float2*)&outB[(m0 + grp + 8) * QS + c] =
                            make_float2(__uint_as_float(f2tf(cB2)), __uint_as_float(f2tf(cB3)));
                    } else {
                        *(float2*)&outA[(m0 + grp + 8) * QS + c] = make_float2(cA2, cA3);
                        *(float2*)&outB[(m0 + grp + 8) * QS + c] = make_float2(cB2, cB3);
                    }
                }
            }
        }
    }
    __syncthreads();

    // ---------------- phase 2+3: attention via mma (warp -> batch bt, head p) ------
    {
        const int h = p;
        const float* spb = smem + QKVR_OFF + bt * 3200;
        const uint32_t* Q = (const uint32_t*)spb;        // tf32 bits
        const uint32_t* K = Q + 800;                     // tf32 bits
        const float*    V = spb + 1600;                  // fp32
        const float*    R = spb + 2400;                  // fp32

        // Q A-frags. Rows 40..47 alias K rows 0..7 — garbage rows, never emitted.
        uint32_t qa[3][4];
        #pragma unroll
        for (int mt = 0; mt < 3; mt++) {
            const int m0 = mt * 16;
            qa[mt][0] = Q[(m0 + grp) * QS + h * 8 + tig];
            qa[mt][1] = Q[(m0 + grp + 8) * QS + h * 8 + tig];
            qa[mt][2] = Q[(m0 + grp) * QS + h * 8 + tig + 4];
            qa[mt][3] = Q[(m0 + grp + 8) * QS + h * 8 + tig + 4];
        }
        uint32_t kb[5][2];
        #pragma unroll
        for (int nt = 0; nt < 5; nt++) {
            kb[nt][0] = K[(nt * 8 + grp) * QS + h * 8 + tig];
            kb[nt][1] = K[(nt * 8 + grp) * QS + h * 8 + tig + 4];
        }

        float o[3][4] = {{0.f}};
        float rsl[3] = {0.f, 0.f, 0.f}, rsh[3] = {0.f, 0.f, 0.f};

        #pragma unroll
        for (int nt = 0; nt < 5; nt++) {
            // V B-frag (bf16x2): rows g = 8nt+2tig, 8nt+2tig+1 ; col h*8+grp.
            // Bank index 8*tig + grp (+8h) mod 32 is a permutation -> conflict-free.
            const float v0 = V[(nt * 8 + 2 * tig) * QS + h * 8 + grp];
            const float v1 = V[(nt * 8 + 2 * tig + 1) * QS + h * 8 + grp];
            const uint32_t vb = pkbf(v0, v1);
            #pragma unroll
            for (int mt = 0; mt < 3; mt++) {
                float c0 = 0.f, c1 = 0.f, c2 = 0.f, c3 = 0.f;
                mma8(c0, c1, c2, c3, qa[mt][0], qa[mt][1], qa[mt][2], qa[mt][3],
                     kb[nt][0], kb[nt][1]);
                const float e0 = __expf(c0), e1 = __expf(c1);
                const float e2 = __expf(c2), e3 = __expf(c3);
                rsl[mt] += e0 + e1;
                rsh[mt] += e2 + e3;
                // fp32 C-frag pairs pack directly into the bf16 A-frag layout.
                const uint32_t pa0 = pkbf(e0, e1);
                const uint32_t pa1 = pkbf(e2, e3);
                mma8bf(o[mt][0], o[mt][1], o[mt][2], o[mt][3], pa0, pa1, vb);
            }
        }

        // row sums: quad-reduce, subtract exact pad-column contribution (e = 1)
        float rl[3], rh[3];
        #pragma unroll
        for (int mt = 0; mt < 3; mt++) {
            float a = rsl[mt], b = rsh[mt];
            a += __shfl_xor_sync(0xffffffffu, a, 1);
            a += __shfl_xor_sync(0xffffffffu, a, 2);
            b += __shfl_xor_sync(0xffffffffu, b, 1);
            b += __shfl_xor_sync(0xffffffffu, b, 2);
            rl[mt] = __fdividef(1.f, a - 1.f);
            rh[mt] = __fdividef(1.f, b - 1.f);
        }

        // epilogue: normalize, + residual, ReLU, store
        float* ob = out + (size_t)(b0 + bt) * (F * 16);
        #pragma unroll
        for (int mt = 0; mt < 3; mt++) {
            const int m0 = mt * 16;
            const int r0 = m0 + grp, r1 = m0 + grp + 8;
            const int c = h * 8 + 2 * tig;
            if (r0 < F) {
                float2 rr = *(float2*)&R[r0 * QS + c];
                float v0 = fmaxf(o[mt][0] * rl[mt] + rr.x, 0.f);
                float v1 = fmaxf(o[mt][1] * rl[mt] + rr.y, 0.f);
                *(float2*)&ob[r0 * 16 + c] = make_float2(v0, v1);
            }
            if (r1 < F) {
                float2 rr = *(float2*)&R[r1 * QS + c];
                float v0 = fmaxf(o[mt][2] * rh[mt] + rr.x, 0.f);
                float v1 = fmaxf(o[mt][3] * rh[mt] + rr.y, 0.f);
                *(float2*)&ob[r1 * 16 + c] = make_float2(v0, v1);
            }
        }
    }
}

extern "C" void kernel_launch(void* const* d_in, const int* in_sizes, int n_in,
                              void* d_out, int out_size)
{
    const float* x  = (const float*)d_in[0];
    const float* Wq = (const float*)d_in[1];
    const float* Wk = (const float*)d_in[2];
    const float* Wv = (const float*)d_in[3];
    const float* Wr = (const float*)d_in[4];
    float* out = (float*)d_out;
    self_attn_mma_kernel<<<B_TOT / 2, NT>>>(x, Wq, Wk, Wv, Wr, out);
}

// round 13
// speedup vs baseline: 2.4025x; 1.0006x over previous
#include <cuda_runtime.h>
#include <cstdint>

#define B_TOT 16384
#define F 39
#define NT 128

// shared-memory layout (float units), total 7744 floats = 30.25 KB -> 7 CTAs/SM
#define SW_OFF   0          // 4 weight mats (tf32 bits), 16x16 row-major, 256 each
#define QKVR_OFF 1024       // 2 batches x {Q,K (tf32 bits), V (fp32)}, 40 rows x stride 20
#define SX_OFF   5824       // x staged as tf32 bits: 2 x 48 x 20
#define SMEM_F   7744
#define QS 20               // row stride: grp*20+tig is a bank permutation

__device__ __forceinline__ uint32_t f2tf(float f) {
    uint32_t r; asm("cvt.rna.tf32.f32 %0, %1;" : "=r"(r) : "f"(f)); return r;
}
// pack {lo, hi} floats -> bf16x2 (lo in lower half)
__device__ __forceinline__ uint32_t pkbf(float lo, float hi) {
    uint32_t r; asm("cvt.rn.bf16x2.f32 %0, %1, %2;" : "=r"(r) : "f"(hi), "f"(lo)); return r;
}
__device__ __forceinline__ void mma8(float& c0, float& c1, float& c2, float& c3,
                                     uint32_t a0, uint32_t a1, uint32_t a2, uint32_t a3,
                                     uint32_t b0, uint32_t b1) {
    asm("mma.sync.aligned.m16n8k8.row.col.f32.tf32.tf32.f32 "
        "{%0,%1,%2,%3}, {%4,%5,%6,%7}, {%8,%9}, {%0,%1,%2,%3};"
        : "+f"(c0), "+f"(c1), "+f"(c2), "+f"(c3)
        : "r"(a0), "r"(a1), "r"(a2), "r"(a3), "r"(b0), "r"(b1));
}
__device__ __forceinline__ void mma8bf(float& c0, float& c1, float& c2, float& c3,
                                       uint32_t a0, uint32_t a1, uint32_t b0) {
    asm("mma.sync.aligned.m16n8k8.row.col.f32.bf16.bf16.f32 "
        "{%0,%1,%2,%3}, {%4,%5}, {%6}, {%0,%1,%2,%3};"
        : "+f"(c0), "+f"(c1), "+f"(c2), "+f"(c3)
        : "r"(a0), "r"(a1), "r"(b0));
}
__device__ __forceinline__ void mma16bf(float& c0, float& c1, float& c2, float& c3,
                                        uint32_t a0, uint32_t a1, uint32_t a2, uint32_t a3,
                                        uint32_t b0, uint32_t b1) {
    asm("mma.sync.aligned.m16n8k16.row.col.f32.bf16.bf16.f32 "
        "{%0,%1,%2,%3}, {%4,%5,%6,%7}, {%8,%9}, {%0,%1,%2,%3};"
        : "+f"(c0), "+f"(c1), "+f"(c2), "+f"(c3)
        : "r"(a0), "r"(a1), "r"(a2), "r"(a3), "r"(b0), "r"(b1));
}

__global__ __launch_bounds__(NT, 7)
void self_attn_mma_kernel(
    const float* __restrict__ x,
    const float* __restrict__ Wq,
    const float* __restrict__ Wk,
    const float* __restrict__ Wv,
    const float* __restrict__ Wr,
    float* __restrict__ out)
{
    __shared__ __align__(16) float smem[SMEM_F];

    const int t    = threadIdx.x;
    const int lane = t & 31;
    const int grp  = lane >> 2;          // 0..7
    const int tig  = lane & 3;           // 0..3
    const int w    = t >> 5;             // warp 0..3
    const int bt   = w >> 1;             // batch within pair
    const int p    = w & 1;              // 0: {Q,K} proj + head 0 ; 1: {V,R} proj + head 1
    const int b0   = blockIdx.x * 2;

    // ---------------- stage: weights + x, pre-converted to tf32 bits ----------
    for (int i = t; i < 256; i += NT) {  // 4 mats x 64 float4
        const int m = i >> 6, r = i & 63;
        const float4* src = (const float4*)(m == 0 ? Wq : m == 1 ? Wk : m == 2 ? Wv : Wr);
        float4 v = src[r];
        ((uint4*)(smem + SW_OFF))[m * 64 + r] =
            make_uint4(f2tf(v.x), f2tf(v.y), f2tf(v.z), f2tf(v.w));
    }
    {
        const float* xb = x + (size_t)b0 * (F * 16);
        for (int i = t; i < 2 * F * 4; i += NT) {
            const int bb = i / (F * 4), r = i - bb * (F * 4);
            const int f = r >> 2, c = r & 3;
            float4 v = ((const float4*)(xb + bb * F * 16 + f * 16))[c];
            *(uint4*)(smem + SX_OFF + bb * 960 + f * QS + c * 4) =
                make_uint4(f2tf(v.x), f2tf(v.y), f2tf(v.z), f2tf(v.w));
        }
        for (int i = t; i < 2 * 9 * 4; i += NT) {   // zero pad rows 39..47
            const int bb = i / 36, r = i - bb * 36;
            const int f = F + (r >> 2), c = r & 3;
            *(uint4*)(smem + SX_OFF + bb * 960 + f * QS + c * 4) = make_uint4(0, 0, 0, 0);
        }
    }
    __syncthreads();

    // ---------------- phase 1: projections via mma (warp -> batch bt, W-pair p) ----
    // p==0: {Q,K} -> smem as tf32 bits. p==1: V -> smem fp32, R -> GLOBAL (out slab).
    {
        float* spb  = smem + QKVR_OFF + bt * 2400;
        float* outA = spb + (p ? 1600 : 0);     // V : Q
        float* outB = spb + 800;                // K (p==0 only)
        float* Rg   = out + (size_t)(b0 + bt) * (F * 16);   // R staging (p==1)
        const uint32_t* WA = (const uint32_t*)(smem + SW_OFF) + (p ? 2 : 0) * 256;
        const uint32_t* WB = (const uint32_t*)(smem + SW_OFF) + (p ? 3 : 1) * 256;
        const uint32_t* sxb = (const uint32_t*)(smem + SX_OFF) + bt * 960;

        uint32_t bA[2][2][2], bB[2][2][2];      // [kt][nt][2], raw tf32 bits
        #pragma unroll
        for (int kt = 0; kt < 2; kt++)
            #pragma unroll
            for (int nt = 0; nt < 2; nt++) {
                bA[kt][nt][0] = WA[(kt * 8 + tig) * 16 + nt * 8 + grp];
                bA[kt][nt][1] = WA[(kt * 8 + tig + 4) * 16 + nt * 8 + grp];
                bB[kt][nt][0] = WB[(kt * 8 + tig) * 16 + nt * 8 + grp];
                bB[kt][nt][1] = WB[(kt * 8 + tig + 4) * 16 + nt * 8 + grp];
            }

        #pragma unroll
        for (int mt = 0; mt < 3; mt++) {
            const int m0 = mt * 16;
            uint32_t a[2][4];
            #pragma unroll
            for (int kt = 0; kt < 2; kt++) {
                a[kt][0] = sxb[(m0 + grp) * QS + kt * 8 + tig];
                a[kt][1] = sxb[(m0 + grp + 8) * QS + kt * 8 + tig];
                a[kt][2] = sxb[(m0 + grp) * QS + kt * 8 + tig + 4];
                a[kt][3] = sxb[(m0 + grp + 8) * QS + kt * 8 + tig + 4];
            }
            #pragma unroll
            for (int nt = 0; nt < 2; nt++) {
                float cA0 = 0.f, cA1 = 0.f, cA2 = 0.f, cA3 = 0.f;
                float cB0 = 0.f, cB1 = 0.f, cB2 = 0.f, cB3 = 0.f;
                mma8(cA0, cA1, cA2, cA3, a[0][0], a[0][1], a[0][2], a[0][3], bA[0][nt][0], bA[0][nt][1]);
                mma8(cA0, cA1, cA2, cA3, a[1][0], a[1][1], a[1][2], a[1][3], bA[1][nt][0], bA[1][nt][1]);
                mma8(cB0, cB1, cB2, cB3, a[0][0], a[0][1], a[0][2], a[0][3], bB[0][nt][0], bB[0][nt][1]);
                mma8(cB0, cB1, cB2, cB3, a[1][0], a[1][1], a[1][2], a[1][3], bB[1][nt][0], bB[1][nt][1]);
                const int c = nt * 8 + 2 * tig;
                const int r0 = m0 + grp, r1 = m0 + grp + 8;
                if (p == 0) {   // Q, K as tf32 bits to smem
                    *(float2*)&outA[r0 * QS + c] =
                        make_float2(__uint_as_float(f2tf(cA0)), __uint_as_float(f2tf(cA1)));
                    *(float2*)&outB[r0 * QS + c] =
                        make_float2(__uint_as_float(f2tf(cB0)), __uint_as_float(f2tf(cB1)));
                    if (mt < 2) {
                        *(float2*)&outA[r1 * QS + c] =
                            make_float2(__uint_as_float(f2tf(cA2)), __uint_as_float(f2tf(cA3)));
                        *(float2*)&outB[r1 * QS + c] =
                            make_float2(__uint_as_float(f2tf(cB2)), __uint_as_float(f2tf(cB3)));
                    }
                } else {        // V fp32 to smem; R fp32 to global (rows < 39 only)
                    *(float2*)&outA[r0 * QS + c] = make_float2(cA0, cA1);
                    if (r0 < F)
                        *(float2*)&Rg[r0 * 16 + c] = make_float2(cB0, cB1);
                    if (mt < 2) {
                        *(float2*)&outA[r1 * QS + c] = make_float2(cA2, cA3);
                        *(float2*)&Rg[r1 * 16 + c] = make_float2(cB2, cB3);
                    }
                }
            }
        }
    }
    __syncthreads();

    // ---------------- phase 2+3: attention via mma (warp -> batch bt, head p) ------
    {
        const int h = p;
        const float* spb = smem + QKVR_OFF + bt * 2400;
        const uint32_t* Q = (const uint32_t*)spb;        // tf32 bits
        const uint32_t* K = Q + 800;                     // tf32 bits
        const float*    V = spb + 1600;                  // fp32
        const float*    Rg = out + (size_t)(b0 + bt) * (F * 16);  // fp32 (global)
        const int hc = h * 8 + grp;

        // Q A-frags. Rows 40..47 alias K rows 0..7 — garbage rows, never emitted.
        uint32_t qa[3][4];
        #pragma unroll
        for (int mt = 0; mt < 3; mt++) {
            const int m0 = mt * 16;
            qa[mt][0] = Q[(m0 + grp) * QS + h * 8 + tig];
            qa[mt][1] = Q[(m0 + grp + 8) * QS + h * 8 + tig];
            qa[mt][2] = Q[(m0 + grp) * QS + h * 8 + tig + 4];
            qa[mt][3] = Q[(m0 + grp + 8) * QS + h * 8 + tig + 4];
        }
        uint32_t kb[5][2];
        #pragma unroll
        for (int nt = 0; nt < 5; nt++) {
            kb[nt][0] = K[(nt * 8 + grp) * QS + h * 8 + tig];
            kb[nt][1] = K[(nt * 8 + grp) * QS + h * 8 + tig + 4];
        }

        float o[3][4] = {{0.f}};
        float rsl[3] = {0.f, 0.f, 0.f}, rsh[3] = {0.f, 0.f, 0.f};

        // nt pairs (0,1), (2,3): k16 PV mma per mt
        #pragma unroll
        for (int j = 0; j < 2; j++) {
            const int r0v = 16 * j;
            const uint32_t vb0 = pkbf(V[(r0v + 2 * tig) * QS + hc],
                                      V[(r0v + 2 * tig + 1) * QS + hc]);
            const uint32_t vb1 = pkbf(V[(r0v + 8 + 2 * tig) * QS + hc],
                                      V[(r0v + 8 + 2 * tig + 1) * QS + hc]);
            #pragma unroll
            for (int mt = 0; mt < 3; mt++) {
                float c0 = 0.f, c1 = 0.f, c2 = 0.f, c3 = 0.f;
                float d0 = 0.f, d1 = 0.f, d2 = 0.f, d3 = 0.f;
                mma8(c0, c1, c2, c3, qa[mt][0], qa[mt][1], qa[mt][2], qa[mt][3],
                     kb[2 * j][0], kb[2 * j][1]);
                mma8(d0, d1, d2, d3, qa[mt][0], qa[mt][1], qa[mt][2], qa[mt][3],
                     kb[2 * j + 1][0], kb[2 * j + 1][1]);
                const float e0 = __expf(c0), e1 = __expf(c1);
                const float e2 = __expf(c2), e3 = __expf(c3);
                const float f0 = __expf(d0), f1 = __expf(d1);
                const float f2 = __expf(d2), f3 = __expf(d3);
                rsl[mt] += (e0 + e1) + (f0 + f1);
                rsh[mt] += (e2 + e3) + (f2 + f3);
                const uint32_t pa0 = pkbf(e0, e1);
                const uint32_t pa1 = pkbf(e2, e3);
                const uint32_t pa2 = pkbf(f0, f1);
                const uint32_t pa3 = pkbf(f2, f3);
                mma16bf(o[mt][0], o[mt][1], o[mt][2], o[mt][3],
                        pa0, pa1, pa2, pa3, vb0, vb1);
            }
        }
        // leftover nt = 4 (rows 32..39): k8 PV mma
        {
            const uint32_t vb = pkbf(V[(32 + 2 * tig) * QS + hc],
                                     V[(32 + 2 * tig + 1) * QS + hc]);
            #pragma unroll
            for (int mt = 0; mt < 3; mt++) {
                float c0 = 0.f, c1 = 0.f, c2 = 0.f, c3 = 0.f;
                mma8(c0, c1, c2, c3, qa[mt][0], qa[mt][1], qa[mt][2], qa[mt][3],
                     kb[4][0], kb[4][1]);
                const float e0 = __expf(c0), e1 = __expf(c1);
                const float e2 = __expf(c2), e3 = __expf(c3);
                rsl[mt] += e0 + e1;
                rsh[mt] += e2 + e3;
                const uint32_t pa0 = pkbf(e0, e1);
                const uint32_t pa1 = pkbf(e2, e3);
                mma8bf(o[mt][0], o[mt][1], o[mt][2], o[mt][3], pa0, pa1, vb);
            }
        }

        // row sums: quad-reduce, subtract exact pad-column contribution (e = 1)
        float rl[3], rh[3];
        #pragma unroll
        for (int mt = 0; mt < 3; mt++) {
            float a = rsl[mt], b = rsh[mt];
            a += __shfl_xor_sync(0xffffffffu, a, 1);
            a += __shfl_xor_sync(0xffffffffu, a, 2);
            b += __shfl_xor_sync(0xffffffffu, b, 1);
            b += __shfl_xor_sync(0xffffffffu, b, 2);
            rl[mt] = __fdividef(1.f, a - 1.f);
            rh[mt] = __fdividef(1.f, b - 1.f);
        }

        // epilogue: normalize, + residual (from out slab), ReLU, store
        float* ob = out + (size_t)(b0 + bt) * (F * 16);
        #pragma unroll
        for (int mt = 0; mt < 3; mt++) {
            const int m0 = mt * 16;
            const int r0 = m0 + grp, r1 = m0 + grp + 8;
            const int c = h * 8 + 2 * tig;
            if (r0 < F) {
                float2 rr = *(float2*)&Rg[r0 * 16 + c];
                float v0 = fmaxf(o[mt][0] * rl[mt] + rr.x, 0.f);
                float v1 = fmaxf(o[mt][1] * rl[mt] + rr.y, 0.f);
                *(float2*)&ob[r0 * 16 + c] = make_float2(v0, v1);
            }
            if (r1 < F) {
                float2 rr = *(float2*)&Rg[r1 * 16 + c];
                float v0 = fmaxf(o[mt][2] * rh[mt] + rr.x, 0.f);
                float v1 = fmaxf(o[mt][3] * rh[mt] + rr.y, 0.f);
                *(float2*)&ob[r1 * 16 + c] = make_float2(v0, v1);
            }
        }
    }
}

extern "C" void kernel_launch(void* const* d_in, const int* in_sizes, int n_in,
                              void* d_out, int out_size)
{
    const float* x  = (const float*)d_in[0];
    const float* Wq = (const float*)d_in[1];
    const float* Wk = (const float*)d_in[2];
    const float* Wv = (const float*)d_in[3];
    const float* Wr = (const float*)d_in[4];
    float* out = (float*)d_out;
    self_attn_mma_kernel<<<B_TOT / 2, NT>>>(x, Wq, Wk, Wv, Wr, out);
}

// round 16
// speedup vs baseline: 2.5010x; 1.0410x over previous
#include <cuda_runtime.h>
#include <cstdint>

// R15 retry: identical to the R14 submission (ones-mma rowsum + ex2); the R15
// run died to a container-infra failure before executing.

#define B_TOT 16384
#define F 39
#define NT 128

// shared-memory layout (float units), total 7744 floats = 30.25 KB
#define SW_OFF   0          // 4 weight mats (tf32 bits), 16x16 row-major, 256 each
#define QKVR_OFF 1024       // 2 batches x {Q,K (tf32 bits), V (fp32)}, 40 rows x stride 20
#define SX_OFF   5824       // x staged as tf32 bits: 2 x 48 x 20
#define SMEM_F   7744
#define QS 20               // row stride: grp*20+tig is a bank permutation

#define ONESBF 0x3F803F80u  // bf16x2 {1.0, 1.0}
#define LOG2E  1.4426950408889634f

__device__ __forceinline__ uint32_t f2tf(float f) {
    uint32_t r; asm("cvt.rna.tf32.f32 %0, %1;" : "=r"(r) : "f"(f)); return r;
}
// MUFU.EX2 directly (device intrinsic __exp2f does not exist)
__device__ __forceinline__ float ex2(float f) {
    float r; asm("ex2.approx.f32 %0, %1;" : "=f"(r) : "f"(f)); return r;
}
// pack {lo, hi} floats -> bf16x2 (lo in lower half)
__device__ __forceinline__ uint32_t pkbf(float lo, float hi) {
    uint32_t r; asm("cvt.rn.bf16x2.f32 %0, %1, %2;" : "=r"(r) : "f"(hi), "f"(lo)); return r;
}
__device__ __forceinline__ void mma8(float& c0, float& c1, float& c2, float& c3,
                                     uint32_t a0, uint32_t a1, uint32_t a2, uint32_t a3,
                                     uint32_t b0, uint32_t b1) {
    asm("mma.sync.aligned.m16n8k8.row.col.f32.tf32.tf32.f32 "
        "{%0,%1,%2,%3}, {%4,%5,%6,%7}, {%8,%9}, {%0,%1,%2,%3};"
        : "+f"(c0), "+f"(c1), "+f"(c2), "+f"(c3)
        : "r"(a0), "r"(a1), "r"(a2), "r"(a3), "r"(b0), "r"(b1));
}
__device__ __forceinline__ void mma8bf(float& c0, float& c1, float& c2, float& c3,
                                       uint32_t a0, uint32_t a1, uint32_t b0) {
    asm("mma.sync.aligned.m16n8k8.row.col.f32.bf16.bf16.f32 "
        "{%0,%1,%2,%3}, {%4,%5}, {%6}, {%0,%1,%2,%3};"
        : "+f"(c0), "+f"(c1), "+f"(c2), "+f"(c3)
        : "r"(a0), "r"(a1), "r"(b0));
}
__device__ __forceinline__ void mma16bf(float& c0, float& c1, float& c2, float& c3,
                                        uint32_t a0, uint32_t a1, uint32_t a2, uint32_t a3,
                                        uint32_t b0, uint32_t b1) {
    asm("mma.sync.aligned.m16n8k16.row.col.f32.bf16.bf16.f32 "
        "{%0,%1,%2,%3}, {%4,%5,%6,%7}, {%8,%9}, {%0,%1,%2,%3};"
        : "+f"(c0), "+f"(c1), "+f"(c2), "+f"(c3)
        : "r"(a0), "r"(a1), "r"(a2), "r"(a3), "r"(b0), "r"(b1));
}

__global__ __launch_bounds__(NT, 6)
void self_attn_mma_kernel(
    const float* __restrict__ x,
    const float* __restrict__ Wq,
    const float* __restrict__ Wk,
    const float* __restrict__ Wv,
    const float* __restrict__ Wr,
    float* __restrict__ out)
{
    __shared__ __align__(16) float smem[SMEM_F];

    const int t    = threadIdx.x;
    const int lane = t & 31;
    const int grp  = lane >> 2;          // 0..7
    const int tig  = lane & 3;           // 0..3
    const int w    = t >> 5;             // warp 0..3
    const int bt   = w >> 1;             // batch within pair
    const int p    = w & 1;              // 0: {Q,K} proj + head 0 ; 1: {V,R} proj + head 1
    const int b0   = blockIdx.x * 2;

    // ---------------- stage: weights + x, pre-converted to tf32 bits ----------
    for (int i = t; i < 256; i += NT) {  // 4 mats x 64 float4
        const int m = i >> 6, r = i & 63;
        const float4* src = (const float4*)(m == 0 ? Wq : m == 1 ? Wk : m == 2 ? Wv : Wr);
        float4 v = src[r];
        ((uint4*)(smem + SW_OFF))[m * 64 + r] =
            make_uint4(f2tf(v.x), f2tf(v.y), f2tf(v.z), f2tf(v.w));
    }
    {
        const float* xb = x + (size_t)b0 * (F * 16);
        for (int i = t; i < 2 * F * 4; i += NT) {
            const int bb = i / (F * 4), r = i - bb * (F * 4);
            const int f = r >> 2, c = r & 3;
            float4 v = ((const float4*)(xb + bb * F * 16 + f * 16))[c];
            *(uint4*)(smem + SX_OFF + bb * 960 + f * QS + c * 4) =
                make_uint4(f2tf(v.x), f2tf(v.y), f2tf(v.z), f2tf(v.w));
        }
        for (int i = t; i < 2 * 9 * 4; i += NT) {   // zero pad rows 39..47
            const int bb = i / 36, r = i - bb * 36;
            const int f = F + (r >> 2), c = r & 3;
            *(uint4*)(smem + SX_OFF + bb * 960 + f * QS + c * 4) = make_uint4(0, 0, 0, 0);
        }
    }
    __syncthreads();

    // ---------------- phase 1: projections via mma (warp -> batch bt, W-pair p) ----
    // p==0: Q -> smem tf32; K -> smem tf32 PRE-SCALED by log2(e) (for exp2 scores).
    // p==1: V -> smem fp32; R -> GLOBAL (out slab) fp32.
    {
        float* spb  = smem + QKVR_OFF + bt * 2400;
        float* outA = spb + (p ? 1600 : 0);     // V : Q
        float* outB = spb + 800;                // K (p==0 only)
        float* Rg   = out + (size_t)(b0 + bt) * (F * 16);   // R staging (p==1)
        const uint32_t* WA = (const uint32_t*)(smem + SW_OFF) + (p ? 2 : 0) * 256;
        const uint32_t* WB = (const uint32_t*)(smem + SW_OFF) + (p ? 3 : 1) * 256;
        const uint32_t* sxb = (const uint32_t*)(smem + SX_OFF) + bt * 960;

        uint32_t bA[2][2][2], bB[2][2][2];      // [kt][nt][2], raw tf32 bits
        #pragma unroll
        for (int kt = 0; kt < 2; kt++)
            #pragma unroll
            for (int nt = 0; nt < 2; nt++) {
                bA[kt][nt][0] = WA[(kt * 8 + tig) * 16 + nt * 8 + grp];
                bA[kt][nt][1] = WA[(kt * 8 + tig + 4) * 16 + nt * 8 + grp];
                bB[kt][nt][0] = WB[(kt * 8 + tig) * 16 + nt * 8 + grp];
                bB[kt][nt][1] = WB[(kt * 8 + tig + 4) * 16 + nt * 8 + grp];
            }

        #pragma unroll
        for (int mt = 0; mt < 3; mt++) {
            const int m0 = mt * 16;
            uint32_t a[2][4];
            #pragma unroll
            for (int kt = 0; kt < 2; kt++) {
                a[kt][0] = sxb[(m0 + grp) * QS + kt * 8 + tig];
                a[kt][1] = sxb[(m0 + grp + 8) * QS + kt * 8 + tig];
                a[kt][2] = sxb[(m0 + grp) * QS + kt * 8 + tig + 4];
                a[kt][3] = sxb[(m0 + grp + 8) * QS + kt * 8 + tig + 4];
            }
            #pragma unroll
            for (int nt = 0; nt < 2; nt++) {
                float cA0 = 0.f, cA1 = 0.f, cA2 = 0.f, cA3 = 0.f;
                float cB0 = 0.f, cB1 = 0.f, cB2 = 0.f, cB3 = 0.f;
                mma8(cA0, cA1, cA2, cA3, a[0][0], a[0][1], a[0][2], a[0][3], bA[0][nt][0], bA[0][nt][1]);
                mma8(cA0, cA1, cA2, cA3, a[1][0], a[1][1], a[1][2], a[1][3], bA[1][nt][0], bA[1][nt][1]);
                mma8(cB0, cB1, cB2, cB3, a[0][0], a[0][1], a[0][2], a[0][3], bB[0][nt][0], bB[0][nt][1]);
                mma8(cB0, cB1, cB2, cB3, a[1][0], a[1][1], a[1][2], a[1][3], bB[1][nt][0], bB[1][nt][1]);
                const int c = nt * 8 + 2 * tig;
                const int r0 = m0 + grp, r1 = m0 + grp + 8;
                if (p == 0) {   // Q tf32 ; K tf32 scaled by log2e
                    *(float2*)&outA[r0 * QS + c] =
                        make_float2(__uint_as_float(f2tf(cA0)), __uint_as_float(f2tf(cA1)));
                    *(float2*)&outB[r0 * QS + c] =
                        make_float2(__uint_as_float(f2tf(cB0 * LOG2E)),
                                    __uint_as_float(f2tf(cB1 * LOG2E)));
                    if (mt < 2) {
                        *(float2*)&outA[r1 * QS + c] =
                            make_float2(__uint_as_float(f2tf(cA2)), __uint_as_float(f2tf(cA3)));
                        *(float2*)&outB[r1 * QS + c] =
                            make_float2(__uint_as_float(f2tf(cB2 * LOG2E)),
                                        __uint_as_float(f2tf(cB3 * LOG2E)));
                    }
                } else {        // V fp32 to smem; R fp32 to global (rows < 39 only)
                    *(float2*)&outA[r0 * QS + c] = make_float2(cA0, cA1);
                    if (r0 < F)
                        *(float2*)&Rg[r0 * 16 + c] = make_float2(cB0, cB1);
                    if (mt < 2) {
                        *(float2*)&outA[r1 * QS + c] = make_float2(cA2, cA3);
                        *(float2*)&Rg[r1 * 16 + c] = make_float2(cB2, cB3);
                    }
                }
            }
        }
    }
    __syncthreads();

    // ---------------- phase 2+3: attention via mma (warp -> batch bt, head p) ------
    {
        const int h = p;
        const float* spb = smem + QKVR_OFF + bt * 2400;
        const uint32_t* Q = (const uint32_t*)spb;        // tf32 bits
        const uint32_t* K = Q + 800;                     // tf32 bits (pre-scaled log2e)
        const float*    V = spb + 1600;                  // fp32
        const float*    Rg = out + (size_t)(b0 + bt) * (F * 16);  // fp32 (global)
        const int hc = h * 8 + grp;

        // Q A-frags. Rows 40..47 alias K rows 0..7 — garbage rows, never emitted.
        uint32_t qa[3][4];
        #pragma unroll
        for (int mt = 0; mt < 3; mt++) {
            const int m0 = mt * 16;
            qa[mt][0] = Q[(m0 + grp) * QS + h * 8 + tig];
            qa[mt][1] = Q[(m0 + grp + 8) * QS + h * 8 + tig];
            qa[mt][2] = Q[(m0 + grp) * QS + h * 8 + tig + 4];
            qa[mt][3] = Q[(m0 + grp + 8) * QS + h * 8 + tig + 4];
        }
        uint32_t kb[5][2];
        #pragma unroll
        for (int nt = 0; nt < 5; nt++) {
            kb[nt][0] = K[(nt * 8 + grp) * QS + h * 8 + tig];
            kb[nt][1] = K[(nt * 8 + grp) * QS + h * 8 + tig + 4];
        }

        float o[3][4]  = {{0.f}};   // PV accumulators
        float rs[3][4] = {{0.f}};   // rowsum accumulators (ones-mma): c0=row grp, c2=row grp+8

        // nt pairs (0,1), (2,3): k16 PV mma + k16 ones-mma per mt
        #pragma unroll
        for (int j = 0; j < 2; j++) {
            const int r0v = 16 * j;
            const uint32_t vb0 = pkbf(V[(r0v + 2 * tig) * QS + hc],
                                      V[(r0v + 2 * tig + 1) * QS + hc]);
            const uint32_t vb1 = pkbf(V[(r0v + 8 + 2 * tig) * QS + hc],
                                      V[(r0v + 8 + 2 * tig + 1) * QS + hc]);
            #pragma unroll
            for (int mt = 0; mt < 3; mt++) {
                float c0 = 0.f, c1 = 0.f, c2 = 0.f, c3 = 0.f;
                float d0 = 0.f, d1 = 0.f, d2 = 0.f, d3 = 0.f;
                mma8(c0, c1, c2, c3, qa[mt][0], qa[mt][1], qa[mt][2], qa[mt][3],
                     kb[2 * j][0], kb[2 * j][1]);
                mma8(d0, d1, d2, d3, qa[mt][0], qa[mt][1], qa[mt][2], qa[mt][3],
                     kb[2 * j + 1][0], kb[2 * j + 1][1]);
                const float e0 = ex2(c0), e1 = ex2(c1);
                const float e2 = ex2(c2), e3 = ex2(c3);
                const float f0 = ex2(d0), f1 = ex2(d1);
                const float f2 = ex2(d2), f3 = ex2(d3);
                const uint32_t pa0 = pkbf(e0, e1);
                const uint32_t pa1 = pkbf(e2, e3);
                const uint32_t pa2 = pkbf(f0, f1);
                const uint32_t pa3 = pkbf(f2, f3);
                mma16bf(o[mt][0], o[mt][1], o[mt][2], o[mt][3],
                        pa0, pa1, pa2, pa3, vb0, vb1);
                mma16bf(rs[mt][0], rs[mt][1], rs[mt][2], rs[mt][3],
                        pa0, pa1, pa2, pa3, ONESBF, ONESBF);
            }
        }
        // leftover nt = 4 (rows 32..39, includes pad col 39): k8 PV + k8 ones-mma
        {
            const uint32_t vb = pkbf(V[(32 + 2 * tig) * QS + hc],
                                     V[(32 + 2 * tig + 1) * QS + hc]);
            #pragma unroll
            for (int mt = 0; mt < 3; mt++) {
                float c0 = 0.f, c1 = 0.f, c2 = 0.f, c3 = 0.f;
                mma8(c0, c1, c2, c3, qa[mt][0], qa[mt][1], qa[mt][2], qa[mt][3],
                     kb[4][0], kb[4][1]);
                const float e0 = ex2(c0), e1 = ex2(c1);
                const float e2 = ex2(c2), e3 = ex2(c3);
                const uint32_t pa0 = pkbf(e0, e1);
                const uint32_t pa1 = pkbf(e2, e3);
                mma8bf(o[mt][0], o[mt][1], o[mt][2], o[mt][3], pa0, pa1, vb);
                mma8bf(rs[mt][0], rs[mt][1], rs[mt][2], rs[mt][3], pa0, pa1, ONESBF);
            }
        }

        // epilogue: normalize (rowsum lives in rs c0/c2; subtract exact pad e=1),
        // + residual (from out slab), ReLU, store
        float* ob = out + (size_t)(b0 + bt) * (F * 16);
        #pragma unroll
        for (int mt = 0; mt < 3; mt++) {
            const int m0 = mt * 16;
            const int r0 = m0 + grp, r1 = m0 + grp + 8;
            const int c = h * 8 + 2 * tig;
            const float rl = __fdividef(1.f, rs[mt][0] - 1.f);
            const float rh = __fdividef(1.f, rs[mt][2] - 1.f);
            if (r0 < F) {
                float2 rr = *(float2*)&Rg[r0 * 16 + c];
                float v0 = fmaxf(o[mt][0] * rl + rr.x, 0.f);
                float v1 = fmaxf(o[mt][1] * rl + rr.y, 0.f);
                *(float2*)&ob[r0 * 16 + c] = make_float2(v0, v1);
            }
            if (r1 < F) {
                float2 rr = *(float2*)&Rg[r1 * 16 + c];
                float v0 = fmaxf(o[mt][2] * rh + rr.x, 0.f);
                float v1 = fmaxf(o[mt][3] * rh + rr.y, 0.f);
                *(float2*)&ob[r1 * 16 + c] = make_float2(v0, v1);
            }
        }
    }
}

extern "C" void kernel_launch(void* const* d_in, const int* in_sizes, int n_in,
                              void* d_out, int out_size)
{
    const float* x  = (const float*)d_in[0];
    const float* Wq = (const float*)d_in[1];
    const float* Wk = (const float*)d_in[2];
    const float* Wv = (const float*)d_in[3];
    const float* Wr = (const float*)d_in[4];
    float* out = (float*)d_out;
    self_attn_mma_kernel<<<B_TOT / 2, NT>>>(x, Wq, Wk, Wv, Wr, out);
}